// round 8
// baseline (speedup 1.0000x reference)
#include <cuda_runtime.h>
#include <cuda_bf16.h>
#include <math.h>

#define NN    10000
#define EE    320000
#define ETOT  330000
#define DIN   256
#define HEADS 8
#define C1    64
#define F1    512
#define F1P   1024            // packed xl|xr GEMM width
#define DOUT  32
#define D2P   64              // packed h2l|h2r row
#define NEG   0.2f

// ---------------- scratch ----------------
__device__ int             g_src[ETOT];
__device__ int             g_dst[ETOT];
__device__ int             g_mode64;
__device__ int             g_deg[NN];
__device__ int             g_off[NN + 1];
__device__ int             g_cur[NN];
__device__ int             g_csrc[ETOT];        // src id sorted by dst
__device__ float           g_W1[DIN * F1P];     // [W1l | W1r] packed
__device__ float           g_W2[F1 * D2P];      // [W2l | W2r] packed
__device__ __nv_bfloat162  g_xlb[NN * (F1 / 2)];// xl half, bf16x2 (gather operand)
__device__ float           g_xr[NN * F1];       // xr half, fp32
__device__ float           g_agg1[NN * F1];     // elu'd h1
__device__ float           g_h2[NN * D2P];      // per node: [h2l(32) | h2r(32)]

__device__ __forceinline__ float lrelu(float v) { return v > 0.f ? v : NEG * v; }

__device__ __forceinline__ float to_tf32(float x) {
    unsigned u;
    asm("cvt.rna.tf32.f32 %0, %1;" : "=r"(u) : "f"(x));
    return __uint_as_float(u);
}

// ---------------- setup: zero deg + dtype probe ----------------
__global__ void k_prep(const void* __restrict__ ei) {
    int i = blockIdx.x * blockDim.x + threadIdx.x;
    if (i < NN) g_deg[i] = 0;
    if (blockIdx.x == 0 && threadIdx.x == 0) {
        const long long* p64 = (const long long*)ei;
        int ok = 1;
        for (int j = 0; j < 64; j++) {
            long long v = p64[j];
            if (v < 0 || v >= NN) { ok = 0; break; }
        }
        g_mode64 = ok;
    }
}

// ---------------- decode + degree count ----------------
__global__ void k_decode_count(const void* __restrict__ ei) {
    int e = blockIdx.x * blockDim.x + threadIdx.x;
    if (e >= ETOT) return;
    int s, d;
    if (e >= EE) { s = d = e - EE; }
    else if (g_mode64) {
        s = (int)((const long long*)ei)[e];
        d = (int)((const long long*)ei)[EE + e];
    } else {
        s = ((const int*)ei)[e];
        d = ((const int*)ei)[EE + e];
    }
    g_src[e] = s;
    g_dst[e] = d;
    atomicAdd(&g_deg[d], 1);
}

// ---------------- scan ----------------
#define SCAN_T 1024
#define SCAN_PER ((NN + SCAN_T - 1) / SCAN_T)
__global__ void k_scan() {
    __shared__ int s[SCAN_T];
    int t = threadIdx.x;
    int base = t * SCAN_PER;
    int sum = 0;
#pragma unroll
    for (int i = 0; i < SCAN_PER; i++) {
        int idx = base + i;
        if (idx < NN) sum += g_deg[idx];
    }
    s[t] = sum;
    __syncthreads();
    for (int o = 1; o < SCAN_T; o <<= 1) {
        int v = (t >= o) ? s[t - o] : 0;
        __syncthreads();
        s[t] += v;
        __syncthreads();
    }
    int run = s[t] - sum;
#pragma unroll
    for (int i = 0; i < SCAN_PER; i++) {
        int idx = base + i;
        if (idx < NN) {
            g_off[idx] = run;
            g_cur[idx] = run;
            run += g_deg[idx];
        }
    }
    if (t == SCAN_T - 1) g_off[NN] = ETOT;
}

__global__ void k_fill() {
    int e = blockIdx.x * blockDim.x + threadIdx.x;
    if (e >= ETOT) return;
    int pos = atomicAdd(&g_cur[g_dst[e]], 1);
    g_csrc[pos] = g_src[e];
}

// ---------------- pack both weight matrices ----------------
#define PACK1 (DIN * F1P)
#define PACK2 (F1 * D2P)
__global__ void k_pack(const float* __restrict__ W1l, const float* __restrict__ W1r,
                       const float* __restrict__ W2l, const float* __restrict__ W2r) {
    int i = blockIdx.x * blockDim.x + threadIdx.x;
    if (i < PACK1) {
        int row = i >> 10, col = i & (F1P - 1);
        g_W1[i] = (col < F1) ? W1l[row * F1 + col] : W1r[row * F1 + col - F1];
    } else if (i < PACK1 + PACK2) {
        int j = i - PACK1;
        int row = j >> 6, col = j & (D2P - 1);
        g_W2[j] = (col < DOUT) ? W2l[row * DOUT + col] : W2r[row * DOUT + col - DOUT];
    }
}

// ---------------- TF32 tensor-core GEMM with split epilogue ----------------
// C = A[M,K] @ B[K,Nc].  Columns < ncols_bf -> bf16x2 store to Cbf (stride ncols_bf/2);
// columns >= ncols_bf -> fp32 store to Cf (stride cf_stride).
#define TBM 128
#define TBN 64
#define TBK 32
__global__ void __launch_bounds__(128) k_gemm_tf32(
    const float* __restrict__ A, const float* __restrict__ B,
    __nv_bfloat162* __restrict__ Cbf, float* __restrict__ Cf,
    int M, int K, int Nc, int ncols_bf, int cf_stride) {
    __shared__ float As[TBK][TBM + 8];
    __shared__ float Bs[TBK][TBN + 8];

    int tid = threadIdx.x;
    int warp = tid >> 5, lane = tid & 31;
    int wm = (warp & 1) * 64;
    int wn = (warp >> 1) * 32;
    int bm = blockIdx.y * TBM, bn = blockIdx.x * TBN;
    int tr = lane >> 2, tc = lane & 3;

    float acc[4][4][4];
#pragma unroll
    for (int mt = 0; mt < 4; mt++)
#pragma unroll
        for (int nt = 0; nt < 4; nt++)
#pragma unroll
            for (int r = 0; r < 4; r++) acc[mt][nt][r] = 0.f;

    int arow = tid;
    int brow = tid >> 2;
    int bcol0 = (tid & 3) * 16;

    for (int k0 = 0; k0 < K; k0 += TBK) {
        if (bm + arow < M) {
            const float* ap = A + (size_t)(bm + arow) * K + k0;
#pragma unroll
            for (int i = 0; i < 8; i++) {
                float4 v = *(const float4*)(ap + i * 4);
                As[i * 4 + 0][arow] = to_tf32(v.x);
                As[i * 4 + 1][arow] = to_tf32(v.y);
                As[i * 4 + 2][arow] = to_tf32(v.z);
                As[i * 4 + 3][arow] = to_tf32(v.w);
            }
        } else {
#pragma unroll
            for (int i = 0; i < 32; i++) As[i][arow] = 0.f;
        }
        {
            const float* bp = B + (size_t)(k0 + brow) * Nc + bn + bcol0;
#pragma unroll
            for (int i = 0; i < 4; i++) {
                float4 v = *(const float4*)(bp + i * 4);
                Bs[brow][bcol0 + i * 4 + 0] = to_tf32(v.x);
                Bs[brow][bcol0 + i * 4 + 1] = to_tf32(v.y);
                Bs[brow][bcol0 + i * 4 + 2] = to_tf32(v.z);
                Bs[brow][bcol0 + i * 4 + 3] = to_tf32(v.w);
            }
        }
        __syncthreads();

#pragma unroll
        for (int ks = 0; ks < TBK / 8; ks++) {
            int kb = ks * 8;
            unsigned af[4][4];
#pragma unroll
            for (int mt = 0; mt < 4; mt++) {
                int m0 = wm + mt * 16;
                af[mt][0] = __float_as_uint(As[kb + tc][m0 + tr]);
                af[mt][1] = __float_as_uint(As[kb + tc][m0 + tr + 8]);
                af[mt][2] = __float_as_uint(As[kb + tc + 4][m0 + tr]);
                af[mt][3] = __float_as_uint(As[kb + tc + 4][m0 + tr + 8]);
            }
            unsigned bf[4][2];
#pragma unroll
            for (int nt = 0; nt < 4; nt++) {
                int n0 = wn + nt * 8;
                bf[nt][0] = __float_as_uint(Bs[kb + tc][n0 + tr]);
                bf[nt][1] = __float_as_uint(Bs[kb + tc + 4][n0 + tr]);
            }
#pragma unroll
            for (int mt = 0; mt < 4; mt++)
#pragma unroll
                for (int nt = 0; nt < 4; nt++) {
                    asm volatile(
                        "mma.sync.aligned.m16n8k8.row.col.f32.tf32.tf32.f32 "
                        "{%0,%1,%2,%3}, {%4,%5,%6,%7}, {%8,%9}, {%0,%1,%2,%3};\n"
                        : "+f"(acc[mt][nt][0]), "+f"(acc[mt][nt][1]),
                          "+f"(acc[mt][nt][2]), "+f"(acc[mt][nt][3])
                        : "r"(af[mt][0]), "r"(af[mt][1]), "r"(af[mt][2]), "r"(af[mt][3]),
                          "r"(bf[nt][0]), "r"(bf[nt][1]));
                }
        }
        __syncthreads();
    }

    bool bf_side = (bn < ncols_bf);   // whole 64-col tile is on one side
#pragma unroll
    for (int mt = 0; mt < 4; mt++) {
        int row0 = bm + wm + mt * 16 + tr;
#pragma unroll
        for (int nt = 0; nt < 4; nt++) {
            int col0 = bn + wn + nt * 8 + 2 * tc;
            if (bf_side) {
                if (row0 < M)
                    g_xlb[(size_t)row0 * (F1 / 2) + (col0 >> 1)] =
                        __floats2bfloat162_rn(acc[mt][nt][0], acc[mt][nt][1]);
                if (row0 + 8 < M)
                    g_xlb[(size_t)(row0 + 8) * (F1 / 2) + (col0 >> 1)] =
                        __floats2bfloat162_rn(acc[mt][nt][2], acc[mt][nt][3]);
            } else {
                int c = col0 - ncols_bf;
                if (row0 < M)
                    *(float2*)(Cf + (size_t)row0 * cf_stride + c) =
                        make_float2(acc[mt][nt][0], acc[mt][nt][1]);
                if (row0 + 8 < M)
                    *(float2*)(Cf + (size_t)(row0 + 8) * cf_stride + c) =
                        make_float2(acc[mt][nt][2], acc[mt][nt][3]);
            }
        }
    }
}

// ---------------- fused layer-1 attention (bf16 gather, online softmax) ----------------
__global__ void k_l1_fused(const float* __restrict__ att1, const float* __restrict__ b1) {
    int node = blockIdx.x;
    int c4 = threadIdx.x;                        // owns channels [4*c4, 4*c4+4)
    int beg = g_off[node], end = g_off[node + 1];

    float4 xr = *(const float4*)(g_xr + (size_t)node * F1 + c4 * 4);
    float4 aw = __ldg(&((const float4*)att1)[c4]);

    float m = -1e30f, den = 0.f;
    float4 acc = make_float4(0.f, 0.f, 0.f, 0.f);

    for (int p = beg; p < end; p++) {
        int src = g_csrc[p];                     // uniform per warp
        const __nv_bfloat162* pb = g_xlb + (size_t)src * (F1 / 2) + c4 * 2;
        float2 f0 = __bfloat1622float2(pb[0]);
        float2 f1 = __bfloat1622float2(pb[1]);
        float part = lrelu(f0.x + xr.x) * aw.x
                   + lrelu(f0.y + xr.y) * aw.y
                   + lrelu(f1.x + xr.z) * aw.z
                   + lrelu(f1.y + xr.w) * aw.w;
#pragma unroll
        for (int o = 8; o; o >>= 1)
            part += __shfl_xor_sync(0xffffffffu, part, o);
        if (part > m) {
            float sc = expf(m - part);
            den *= sc;
            acc.x *= sc; acc.y *= sc; acc.z *= sc; acc.w *= sc;
            m = part;
        }
        float w = expf(part - m);
        den += w;
        acc.x += w * f0.x; acc.y += w * f0.y; acc.z += w * f1.x; acc.w += w * f1.y;
    }
    float inv = 1.f / (den + 1e-16f);
    float4 bb = __ldg(&((const float4*)b1)[c4]);
    float r0 = acc.x * inv + bb.x;
    float r1 = acc.y * inv + bb.y;
    float r2 = acc.z * inv + bb.z;
    float r3 = acc.w * inv + bb.w;
    r0 = r0 > 0.f ? r0 : expm1f(r0);
    r1 = r1 > 0.f ? r1 : expm1f(r1);
    r2 = r2 > 0.f ? r2 : expm1f(r2);
    r3 = r3 > 0.f ? r3 : expm1f(r3);
    *(float4*)(g_agg1 + (size_t)node * F1 + c4 * 4) = make_float4(r0, r1, r2, r3);
}

// ---------------- fused layer-2 attention + bias + log_softmax ----------------
__global__ void k_l2_fused(float* __restrict__ out, const float* __restrict__ att2,
                           const float* __restrict__ b2) {
    int node = (blockIdx.x * blockDim.x + threadIdx.x) >> 5;
    int lane = threadIdx.x & 31;
    if (node >= NN) return;
    int beg = g_off[node], end = g_off[node + 1];

    float xr = g_h2[(size_t)node * D2P + DOUT + lane];
    float aw = __ldg(att2 + lane);

    float m = -1e30f, den = 0.f, acc = 0.f;
    for (int p = beg; p < end; p++) {
        int src = g_csrc[p];
        float v = g_h2[(size_t)src * D2P + lane];
        float part = lrelu(v + xr) * aw;
#pragma unroll
        for (int o = 16; o; o >>= 1)
            part += __shfl_xor_sync(0xffffffffu, part, o);
        if (part > m) {
            float sc = expf(m - part);
            den *= sc; acc *= sc; m = part;
        }
        float w = expf(part - m);
        den += w;
        acc += w * v;
    }
    float v = acc / (den + 1e-16f) + __ldg(b2 + lane);
    float mx = v;
#pragma unroll
    for (int o = 16; o; o >>= 1) mx = fmaxf(mx, __shfl_xor_sync(0xffffffffu, mx, o));
    float s = expf(v - mx);
#pragma unroll
    for (int o = 16; o; o >>= 1) s += __shfl_xor_sync(0xffffffffu, s, o);
    out[node * DOUT + lane] = v - mx - logf(s);
}

// ---------------- launch ----------------
extern "C" void kernel_launch(void* const* d_in, const int* in_sizes, int n_in,
                              void* d_out, int out_size) {
    const float* x    = (const float*)d_in[0];
    const void*  ei   = d_in[1];
    const float* W1l  = (const float*)d_in[2];
    const float* W1r  = (const float*)d_in[3];
    const float* att1 = (const float*)d_in[4];
    const float* b1   = (const float*)d_in[5];
    const float* W2l  = (const float*)d_in[6];
    const float* W2r  = (const float*)d_in[7];
    const float* att2 = (const float*)d_in[8];
    const float* b2   = (const float*)d_in[9];
    float*       out  = (float*)d_out;

    const int TPB = 256;

    float *W1p, *W2p, *xr, *h1, *h2;
    cudaGetSymbolAddress((void**)&W1p, g_W1);
    cudaGetSymbolAddress((void**)&W2p, g_W2);
    cudaGetSymbolAddress((void**)&xr,  g_xr);
    cudaGetSymbolAddress((void**)&h1,  g_agg1);
    cudaGetSymbolAddress((void**)&h2,  g_h2);

    // 1-5: setup
    k_prep<<<(NN + TPB - 1) / TPB, TPB>>>(ei);
    k_decode_count<<<(ETOT + TPB - 1) / TPB, TPB>>>(ei);
    k_scan<<<1, SCAN_T>>>();
    k_fill<<<(ETOT + TPB - 1) / TPB, TPB>>>();
    k_pack<<<(PACK1 + PACK2 + TPB - 1) / TPB, TPB>>>(W1l, W1r, W2l, W2r);

    // 6: layer-1 GEMM (xl -> bf16, xr -> fp32)
    {
        dim3 grid(F1P / TBN, (NN + TBM - 1) / TBM);
        k_gemm_tf32<<<grid, 128>>>(x, W1p, nullptr, xr, NN, DIN, F1P, F1, F1);
    }
    // 7: layer-1 fused attention -> h1
    k_l1_fused<<<NN, 128>>>(att1, b1);

    // 8: layer-2 GEMM (all fp32 -> g_h2)
    {
        dim3 grid(D2P / TBN, (NN + TBM - 1) / TBM);
        k_gemm_tf32<<<grid, 128>>>(h1, W2p, nullptr, h2, NN, F1, D2P, 0, D2P);
    }
    // 9: layer-2 fused attention + output
    k_l2_fused<<<(NN * 32 + TPB - 1) / TPB, TPB>>>(out, att2, b2);
}

// round 11
// speedup vs baseline: 1.0348x; 1.0348x over previous
#include <cuda_runtime.h>
#include <cuda_bf16.h>
#include <math.h>

#define NN    10000
#define EE    320000
#define ETOT  330000
#define DIN   256
#define HEADS 8
#define C1    64
#define F1    512
#define F1P   1024            // packed xl|xr GEMM width
#define DOUT  32
#define D2P   64              // packed h2l|h2r row
#define NEG   0.2f

// ---------------- scratch ----------------
__device__ int             g_src[ETOT];
__device__ int             g_dst[ETOT];
__device__ int             g_mode64;
__device__ int             g_deg[NN];
__device__ int             g_off[NN + 1];
__device__ int             g_cur[NN];
__device__ int             g_csrc[ETOT];        // src id sorted by dst
__device__ float           g_W1[DIN * F1P];     // [W1l | W1r] packed
__device__ float           g_W2[F1 * D2P];      // [W2l | W2r] packed
__device__ __nv_bfloat162  g_xlb[NN * (F1 / 2)];// xl half, bf16x2 (gather operand)
__device__ float           g_xr[NN * F1];       // xr half, fp32
__device__ float           g_agg1[NN * F1];     // elu'd h1
__device__ float           g_h2[NN * D2P];      // per node: [h2l(32) | h2r(32)]

__device__ __forceinline__ float lrelu(float v) { return v > 0.f ? v : NEG * v; }

__device__ __forceinline__ float to_tf32(float x) {
    unsigned u;
    asm("cvt.rna.tf32.f32 %0, %1;" : "=r"(u) : "f"(x));
    return __uint_as_float(u);
}

// ---------------- setup: zero deg + dtype probe ----------------
__global__ void k_prep(const void* __restrict__ ei) {
    int i = blockIdx.x * blockDim.x + threadIdx.x;
    if (i < NN) g_deg[i] = 0;
    if (blockIdx.x == 0 && threadIdx.x == 0) {
        const long long* p64 = (const long long*)ei;
        int ok = 1;
        for (int j = 0; j < 64; j++) {
            long long v = p64[j];
            if (v < 0 || v >= NN) { ok = 0; break; }
        }
        g_mode64 = ok;
    }
}

// ---------------- decode + degree count ----------------
__global__ void k_decode_count(const void* __restrict__ ei) {
    int e = blockIdx.x * blockDim.x + threadIdx.x;
    if (e >= ETOT) return;
    int s, d;
    if (e >= EE) { s = d = e - EE; }
    else if (g_mode64) {
        s = (int)((const long long*)ei)[e];
        d = (int)((const long long*)ei)[EE + e];
    } else {
        s = ((const int*)ei)[e];
        d = ((const int*)ei)[EE + e];
    }
    g_src[e] = s;
    g_dst[e] = d;
    atomicAdd(&g_deg[d], 1);
}

// ---------------- scan ----------------
#define SCAN_T 1024
#define SCAN_PER ((NN + SCAN_T - 1) / SCAN_T)
__global__ void k_scan() {
    __shared__ int s[SCAN_T];
    int t = threadIdx.x;
    int base = t * SCAN_PER;
    int sum = 0;
#pragma unroll
    for (int i = 0; i < SCAN_PER; i++) {
        int idx = base + i;
        if (idx < NN) sum += g_deg[idx];
    }
    s[t] = sum;
    __syncthreads();
    for (int o = 1; o < SCAN_T; o <<= 1) {
        int v = (t >= o) ? s[t - o] : 0;
        __syncthreads();
        s[t] += v;
        __syncthreads();
    }
    int run = s[t] - sum;
#pragma unroll
    for (int i = 0; i < SCAN_PER; i++) {
        int idx = base + i;
        if (idx < NN) {
            g_off[idx] = run;
            g_cur[idx] = run;
            run += g_deg[idx];
        }
    }
    if (t == SCAN_T - 1) g_off[NN] = ETOT;
}

__global__ void k_fill() {
    int e = blockIdx.x * blockDim.x + threadIdx.x;
    if (e >= ETOT) return;
    int pos = atomicAdd(&g_cur[g_dst[e]], 1);
    g_csrc[pos] = g_src[e];
}

// ---------------- pack both weight matrices ----------------
#define PACK1 (DIN * F1P)
#define PACK2 (F1 * D2P)
__global__ void k_pack(const float* __restrict__ W1l, const float* __restrict__ W1r,
                       const float* __restrict__ W2l, const float* __restrict__ W2r) {
    int i = blockIdx.x * blockDim.x + threadIdx.x;
    if (i < PACK1) {
        int row = i >> 10, col = i & (F1P - 1);
        g_W1[i] = (col < F1) ? W1l[row * F1 + col] : W1r[row * F1 + col - F1];
    } else if (i < PACK1 + PACK2) {
        int j = i - PACK1;
        int row = j >> 6, col = j & (D2P - 1);
        g_W2[j] = (col < DOUT) ? W2l[row * DOUT + col] : W2r[row * DOUT + col - DOUT];
    }
}

// ---------------- TF32 tensor-core GEMM with split epilogue ----------------
// C = A[M,K] @ B[K,Nc].  Columns < ncols_bf -> bf16x2 to g_xlb; rest -> fp32 Cf.
#define TBM 128
#define TBN 64
#define TBK 32
__global__ void __launch_bounds__(128) k_gemm_tf32(
    const float* __restrict__ A, const float* __restrict__ B,
    float* __restrict__ Cf,
    int M, int K, int Nc, int ncols_bf, int cf_stride) {
    __shared__ float As[TBK][TBM + 8];
    __shared__ float Bs[TBK][TBN + 8];

    int tid = threadIdx.x;
    int warp = tid >> 5, lane = tid & 31;
    int wm = (warp & 1) * 64;
    int wn = (warp >> 1) * 32;
    int bm = blockIdx.y * TBM, bn = blockIdx.x * TBN;
    int tr = lane >> 2, tc = lane & 3;

    float acc[4][4][4];
#pragma unroll
    for (int mt = 0; mt < 4; mt++)
#pragma unroll
        for (int nt = 0; nt < 4; nt++)
#pragma unroll
            for (int r = 0; r < 4; r++) acc[mt][nt][r] = 0.f;

    int arow = tid;
    int brow = tid >> 2;
    int bcol0 = (tid & 3) * 16;

    for (int k0 = 0; k0 < K; k0 += TBK) {
        if (bm + arow < M) {
            const float* ap = A + (size_t)(bm + arow) * K + k0;
#pragma unroll
            for (int i = 0; i < 8; i++) {
                float4 v = *(const float4*)(ap + i * 4);
                As[i * 4 + 0][arow] = to_tf32(v.x);
                As[i * 4 + 1][arow] = to_tf32(v.y);
                As[i * 4 + 2][arow] = to_tf32(v.z);
                As[i * 4 + 3][arow] = to_tf32(v.w);
            }
        } else {
#pragma unroll
            for (int i = 0; i < 32; i++) As[i][arow] = 0.f;
        }
        {
            const float* bp = B + (size_t)(k0 + brow) * Nc + bn + bcol0;
#pragma unroll
            for (int i = 0; i < 4; i++) {
                float4 v = *(const float4*)(bp + i * 4);
                Bs[brow][bcol0 + i * 4 + 0] = to_tf32(v.x);
                Bs[brow][bcol0 + i * 4 + 1] = to_tf32(v.y);
                Bs[brow][bcol0 + i * 4 + 2] = to_tf32(v.z);
                Bs[brow][bcol0 + i * 4 + 3] = to_tf32(v.w);
            }
        }
        __syncthreads();

#pragma unroll
        for (int ks = 0; ks < TBK / 8; ks++) {
            int kb = ks * 8;
            unsigned af[4][4];
#pragma unroll
            for (int mt = 0; mt < 4; mt++) {
                int m0 = wm + mt * 16;
                af[mt][0] = __float_as_uint(As[kb + tc][m0 + tr]);
                af[mt][1] = __float_as_uint(As[kb + tc][m0 + tr + 8]);
                af[mt][2] = __float_as_uint(As[kb + tc + 4][m0 + tr]);
                af[mt][3] = __float_as_uint(As[kb + tc + 4][m0 + tr + 8]);
            }
            unsigned bf[4][2];
#pragma unroll
            for (int nt = 0; nt < 4; nt++) {
                int n0 = wn + nt * 8;
                bf[nt][0] = __float_as_uint(Bs[kb + tc][n0 + tr]);
                bf[nt][1] = __float_as_uint(Bs[kb + tc + 4][n0 + tr]);
            }
#pragma unroll
            for (int mt = 0; mt < 4; mt++)
#pragma unroll
                for (int nt = 0; nt < 4; nt++) {
                    asm volatile(
                        "mma.sync.aligned.m16n8k8.row.col.f32.tf32.tf32.f32 "
                        "{%0,%1,%2,%3}, {%4,%5,%6,%7}, {%8,%9}, {%0,%1,%2,%3};\n"
                        : "+f"(acc[mt][nt][0]), "+f"(acc[mt][nt][1]),
                          "+f"(acc[mt][nt][2]), "+f"(acc[mt][nt][3])
                        : "r"(af[mt][0]), "r"(af[mt][1]), "r"(af[mt][2]), "r"(af[mt][3]),
                          "r"(bf[nt][0]), "r"(bf[nt][1]));
                }
        }
        __syncthreads();
    }

    bool bf_side = (bn < ncols_bf);   // whole 64-col tile is on one side
#pragma unroll
    for (int mt = 0; mt < 4; mt++) {
        int row0 = bm + wm + mt * 16 + tr;
#pragma unroll
        for (int nt = 0; nt < 4; nt++) {
            int col0 = bn + wn + nt * 8 + 2 * tc;
            if (bf_side) {
                if (row0 < M)
                    g_xlb[(size_t)row0 * (F1 / 2) + (col0 >> 1)] =
                        __floats2bfloat162_rn(acc[mt][nt][0], acc[mt][nt][1]);
                if (row0 + 8 < M)
                    g_xlb[(size_t)(row0 + 8) * (F1 / 2) + (col0 >> 1)] =
                        __floats2bfloat162_rn(acc[mt][nt][2], acc[mt][nt][3]);
            } else {
                int c = col0 - ncols_bf;
                if (row0 < M)
                    *(float2*)(Cf + (size_t)row0 * cf_stride + c) =
                        make_float2(acc[mt][nt][0], acc[mt][nt][1]);
                if (row0 + 8 < M)
                    *(float2*)(Cf + (size_t)(row0 + 8) * cf_stride + c) =
                        make_float2(acc[mt][nt][2], acc[mt][nt][3]);
            }
        }
    }
}

// ---------------- fused layer-1 attention (bf16 gather, online softmax) ----------------
__global__ void k_l1_fused(const float* __restrict__ att1, const float* __restrict__ b1) {
    int node = blockIdx.x;
    int c4 = threadIdx.x;                        // owns channels [4*c4, 4*c4+4)
    int beg = g_off[node], end = g_off[node + 1];

    float4 xr = *(const float4*)(g_xr + (size_t)node * F1 + c4 * 4);
    float4 aw = __ldg(&((const float4*)att1)[c4]);

    float m = -1e30f, den = 0.f;
    float4 acc = make_float4(0.f, 0.f, 0.f, 0.f);

    for (int p = beg; p < end; p++) {
        int src = g_csrc[p];                     // uniform per warp
        // single 8-byte vector load of 4 bf16 channels
        uint2 raw = *(const uint2*)(g_xlb + (size_t)src * (F1 / 2) + c4 * 2);
        float2 f0 = __bfloat1622float2(*(const __nv_bfloat162*)&raw.x);
        float2 f1 = __bfloat1622float2(*(const __nv_bfloat162*)&raw.y);
        float part = lrelu(f0.x + xr.x) * aw.x
                   + lrelu(f0.y + xr.y) * aw.y
                   + lrelu(f1.x + xr.z) * aw.z
                   + lrelu(f1.y + xr.w) * aw.w;
#pragma unroll
        for (int o = 8; o; o >>= 1)
            part += __shfl_xor_sync(0xffffffffu, part, o);
        if (part > m) {
            float sc = __expf(m - part);
            den *= sc;
            acc.x *= sc; acc.y *= sc; acc.z *= sc; acc.w *= sc;
            m = part;
        }
        float w = __expf(part - m);
        den += w;
        acc.x += w * f0.x; acc.y += w * f0.y; acc.z += w * f1.x; acc.w += w * f1.y;
    }
    float inv = 1.f / (den + 1e-16f);
    float4 bb = __ldg(&((const float4*)b1)[c4]);
    float r0 = acc.x * inv + bb.x;
    float r1 = acc.y * inv + bb.y;
    float r2 = acc.z * inv + bb.z;
    float r3 = acc.w * inv + bb.w;
    r0 = r0 > 0.f ? r0 : expm1f(r0);
    r1 = r1 > 0.f ? r1 : expm1f(r1);
    r2 = r2 > 0.f ? r2 : expm1f(r2);
    r3 = r3 > 0.f ? r3 : expm1f(r3);
    *(float4*)(g_agg1 + (size_t)node * F1 + c4 * 4) = make_float4(r0, r1, r2, r3);
}

// ---------------- fused layer-2 attention + bias + log_softmax ----------------
__global__ void k_l2_fused(float* __restrict__ out, const float* __restrict__ att2,
                           const float* __restrict__ b2) {
    int node = (blockIdx.x * blockDim.x + threadIdx.x) >> 5;
    int lane = threadIdx.x & 31;
    if (node >= NN) return;
    int beg = g_off[node], end = g_off[node + 1];

    float xr = g_h2[(size_t)node * D2P + DOUT + lane];
    float aw = __ldg(att2 + lane);

    float m = -1e30f, den = 0.f, acc = 0.f;
    for (int p = beg; p < end; p++) {
        int src = g_csrc[p];
        float v = g_h2[(size_t)src * D2P + lane];
        float part = lrelu(v + xr) * aw;
#pragma unroll
        for (int o = 16; o; o >>= 1)
            part += __shfl_xor_sync(0xffffffffu, part, o);
        if (part > m) {
            float sc = __expf(m - part);
            den *= sc; acc *= sc; m = part;
        }
        float w = __expf(part - m);
        den += w;
        acc += w * v;
    }
    float v = acc / (den + 1e-16f) + __ldg(b2 + lane);
    float mx = v;
#pragma unroll
    for (int o = 16; o; o >>= 1) mx = fmaxf(mx, __shfl_xor_sync(0xffffffffu, mx, o));
    float s = __expf(v - mx);
#pragma unroll
    for (int o = 16; o; o >>= 1) s += __shfl_xor_sync(0xffffffffu, s, o);
    out[node * DOUT + lane] = v - mx - __logf(s);
}

// ---------------- launch ----------------
extern "C" void kernel_launch(void* const* d_in, const int* in_sizes, int n_in,
                              void* d_out, int out_size) {
    const float* x    = (const float*)d_in[0];
    const void*  ei   = d_in[1];
    const float* W1l  = (const float*)d_in[2];
    const float* W1r  = (const float*)d_in[3];
    const float* att1 = (const float*)d_in[4];
    const float* b1   = (const float*)d_in[5];
    const float* W2l  = (const float*)d_in[6];
    const float* W2r  = (const float*)d_in[7];
    const float* att2 = (const float*)d_in[8];
    const float* b2   = (const float*)d_in[9];
    float*       out  = (float*)d_out;

    const int TPB = 256;

    float *W1p, *W2p, *xr, *h1, *h2;
    cudaGetSymbolAddress((void**)&W1p, g_W1);
    cudaGetSymbolAddress((void**)&W2p, g_W2);
    cudaGetSymbolAddress((void**)&xr,  g_xr);
    cudaGetSymbolAddress((void**)&h1,  g_agg1);
    cudaGetSymbolAddress((void**)&h2,  g_h2);

    // order chosen so the hot GEMM is the 4th launch (ncu -s 5 lands there)
    k_prep<<<(NN + TPB - 1) / TPB, TPB>>>(ei);                         // 1
    k_decode_count<<<(ETOT + TPB - 1) / TPB, TPB>>>(ei);               // 2
    k_pack<<<(PACK1 + PACK2 + TPB - 1) / TPB, TPB>>>(W1l, W1r, W2l, W2r); // 3
    {
        dim3 grid(F1P / TBN, (NN + TBM - 1) / TBM);
        k_gemm_tf32<<<grid, 128>>>(x, W1p, xr, NN, DIN, F1P, F1, F1);  // 4
    }
    k_scan<<<1, SCAN_T>>>();                                           // 5
    k_fill<<<(ETOT + TPB - 1) / TPB, TPB>>>();                         // 6
    k_l1_fused<<<NN, 128>>>(att1, b1);                                 // 7
    {
        dim3 grid(D2P / TBN, (NN + TBM - 1) / TBM);
        k_gemm_tf32<<<grid, 128>>>(h1, W2p, h2, NN, F1, D2P, 0, D2P);  // 8
    }
    k_l2_fused<<<(NN * 32 + TPB - 1) / TPB, TPB>>>(out, att2, b2);     // 9
}

// round 12
// speedup vs baseline: 1.1928x; 1.1527x over previous
#include <cuda_runtime.h>
#include <cuda_bf16.h>
#include <math.h>

#define NN    10000
#define EE    320000
#define ETOT  330000
#define DIN   256
#define HEADS 8
#define C1    64
#define F1    512
#define F1P   1024            // packed xl|xr GEMM width
#define DOUT  32
#define D2P   64              // packed h2l|h2r row
#define NEG   0.2f

// ---------------- scratch ----------------
__device__ int             g_src[ETOT];
__device__ int             g_dst[ETOT];
__device__ int             g_mode64;
__device__ int             g_deg[NN];
__device__ int             g_off[NN + 1];
__device__ int             g_cur[NN];
__device__ int             g_csrc[ETOT];          // src id sorted by dst
__device__ __nv_bfloat16   g_W1Tb[F1P * DIN];     // [n][k] transposed bf16 [1024][256]
__device__ __nv_bfloat16   g_W2Tb[D2P * F1];      // [n][k] transposed bf16 [64][512]
__device__ __nv_bfloat162  g_xlb[NN * (F1 / 2)];  // xl half, bf16x2 (gather operand)
__device__ float           g_xr[NN * F1];         // xr half, fp32
__device__ __nv_bfloat16   g_h1b[NN * F1];        // elu'd h1, bf16 (GEMM2 A operand)
__device__ float           g_h2[NN * D2P];        // per node: [h2l(32) | h2r(32)]

__device__ __forceinline__ float lrelu(float v) { return v > 0.f ? v : NEG * v; }

// ---------------- setup: zero deg + dtype probe ----------------
__global__ void k_prep(const void* __restrict__ ei) {
    int i = blockIdx.x * blockDim.x + threadIdx.x;
    if (i < NN) g_deg[i] = 0;
    if (blockIdx.x == 0 && threadIdx.x == 0) {
        const long long* p64 = (const long long*)ei;
        int ok = 1;
        for (int j = 0; j < 64; j++) {
            long long v = p64[j];
            if (v < 0 || v >= NN) { ok = 0; break; }
        }
        g_mode64 = ok;
    }
}

// ---------------- decode + degree count ----------------
__global__ void k_decode_count(const void* __restrict__ ei) {
    int e = blockIdx.x * blockDim.x + threadIdx.x;
    if (e >= ETOT) return;
    int s, d;
    if (e >= EE) { s = d = e - EE; }
    else if (g_mode64) {
        s = (int)((const long long*)ei)[e];
        d = (int)((const long long*)ei)[EE + e];
    } else {
        s = ((const int*)ei)[e];
        d = ((const int*)ei)[EE + e];
    }
    g_src[e] = s;
    g_dst[e] = d;
    atomicAdd(&g_deg[d], 1);
}

// ---------------- scan ----------------
#define SCAN_T 1024
#define SCAN_PER ((NN + SCAN_T - 1) / SCAN_T)
__global__ void k_scan() {
    __shared__ int s[SCAN_T];
    int t = threadIdx.x;
    int base = t * SCAN_PER;
    int sum = 0;
#pragma unroll
    for (int i = 0; i < SCAN_PER; i++) {
        int idx = base + i;
        if (idx < NN) sum += g_deg[idx];
    }
    s[t] = sum;
    __syncthreads();
    for (int o = 1; o < SCAN_T; o <<= 1) {
        int v = (t >= o) ? s[t - o] : 0;
        __syncthreads();
        s[t] += v;
        __syncthreads();
    }
    int run = s[t] - sum;
#pragma unroll
    for (int i = 0; i < SCAN_PER; i++) {
        int idx = base + i;
        if (idx < NN) {
            g_off[idx] = run;
            g_cur[idx] = run;
            run += g_deg[idx];
        }
    }
    if (t == SCAN_T - 1) g_off[NN] = ETOT;
}

__global__ void k_fill() {
    int e = blockIdx.x * blockDim.x + threadIdx.x;
    if (e >= ETOT) return;
    int pos = atomicAdd(&g_cur[g_dst[e]], 1);
    g_csrc[pos] = g_src[e];
}

// ---------------- transpose-pack weights to bf16 [n][k] ----------------
// W1: W1l/W1r are [256][512] -> g_W1Tb[1024][256]
__global__ void k_packT1(const float* __restrict__ W1l, const float* __restrict__ W1r) {
    __shared__ float tile[32][33];
    int n0 = blockIdx.x * 32, k0 = blockIdx.y * 32;
    int tx = threadIdx.x, ty = threadIdx.y;
#pragma unroll
    for (int i = 0; i < 32; i += 8) {
        int k = k0 + ty + i, n = n0 + tx;
        float v = (n < F1) ? W1l[k * F1 + n] : W1r[k * F1 + (n - F1)];
        tile[ty + i][tx] = v;          // tile[k][n]
    }
    __syncthreads();
#pragma unroll
    for (int i = 0; i < 32; i += 8) {
        int n = n0 + ty + i, k = k0 + tx;
        g_W1Tb[(size_t)n * DIN + k] = __float2bfloat16(tile[tx][ty + i]);
    }
}
// W2: W2l/W2r are [512][32] -> g_W2Tb[64][512]
__global__ void k_packT2(const float* __restrict__ W2l, const float* __restrict__ W2r) {
    __shared__ float tile[32][33];
    int n0 = blockIdx.x * 32, k0 = blockIdx.y * 32;
    int tx = threadIdx.x, ty = threadIdx.y;
#pragma unroll
    for (int i = 0; i < 32; i += 8) {
        int k = k0 + ty + i, n = n0 + tx;
        float v = (n < DOUT) ? W2l[k * DOUT + n] : W2r[k * DOUT + (n - DOUT)];
        tile[ty + i][tx] = v;
    }
    __syncthreads();
#pragma unroll
    for (int i = 0; i < 32; i += 8) {
        int n = n0 + ty + i, k = k0 + tx;
        g_W2Tb[(size_t)n * F1 + k] = __float2bfloat16(tile[tx][ty + i]);
    }
}

// ---------------- bf16 tensor-core GEMM (ldmatrix + m16n8k16) ----------------
// C = A[M,K] @ Bt^T where Bt is [Nc][K] bf16 (n-major).
// A: fp32 (Af) if a_bf16==0 else bf16 (Ab).
// Epilogue: cols < ncols_bf -> bf16x2 to g_xlb; rest -> fp32 Cf (stride cf_stride).
#define TBM 128
#define TBN 64
#define TBK 64
__device__ __forceinline__ void ldsm_x4(unsigned& r0, unsigned& r1, unsigned& r2, unsigned& r3,
                                        const void* p) {
    unsigned addr = (unsigned)__cvta_generic_to_shared(p);
    asm volatile("ldmatrix.sync.aligned.m8n8.x4.shared.b16 {%0,%1,%2,%3}, [%4];"
                 : "=r"(r0), "=r"(r1), "=r"(r2), "=r"(r3) : "r"(addr));
}

__global__ void __launch_bounds__(128) k_gemm_bf16(
    const float* __restrict__ Af, const __nv_bfloat16* __restrict__ Ab,
    const __nv_bfloat16* __restrict__ Bt, float* __restrict__ Cf,
    int M, int K, int a_bf16, int ncols_bf, int cf_stride) {
    __shared__ __nv_bfloat16 As[TBM][TBK + 8];   // [m][k]
    __shared__ __nv_bfloat16 Bs[TBN][TBK + 8];   // [n][k]

    int tid = threadIdx.x;
    int warp = tid >> 5, lane = tid & 31;
    int wm = (warp & 1) * 64;
    int wn = (warp >> 1) * 32;
    int bm = blockIdx.y * TBM, bn = blockIdx.x * TBN;
    int tr = lane >> 2, tc = lane & 3;

    float acc[4][4][4];
#pragma unroll
    for (int mt = 0; mt < 4; mt++)
#pragma unroll
        for (int nt = 0; nt < 4; nt++)
#pragma unroll
            for (int r = 0; r < 4; r++) acc[mt][nt][r] = 0.f;

    int brow_n = tid & 63;        // B fill: n index
    int bhalf  = tid >> 6;        // 0/1 -> k half

    for (int k0 = 0; k0 < K; k0 += TBK) {
        // ---- fill A tile (row = tid) ----
        int row = tid;
        if (bm + row < M) {
            if (a_bf16) {
                const uint4* ap = (const uint4*)(Ab + (size_t)(bm + row) * K + k0);
#pragma unroll
                for (int i = 0; i < 8; i++)
                    *(uint4*)&As[row][i * 8] = ap[i];
            } else {
                const float4* ap = (const float4*)(Af + (size_t)(bm + row) * K + k0);
#pragma unroll
                for (int i = 0; i < 16; i++) {
                    float4 v = ap[i];
                    __nv_bfloat162 p0 = __floats2bfloat162_rn(v.x, v.y);
                    __nv_bfloat162 p1 = __floats2bfloat162_rn(v.z, v.w);
                    uint2 pk;
                    pk.x = *(unsigned*)&p0;
                    pk.y = *(unsigned*)&p1;
                    *(uint2*)&As[row][i * 4] = pk;
                }
            }
        } else {
            uint4 z = make_uint4(0, 0, 0, 0);
#pragma unroll
            for (int i = 0; i < 8; i++)
                *(uint4*)&As[row][i * 8] = z;
        }
        // ---- fill B tile: Bs[n][k] from Bt[bn+n][k0..] (contiguous bf16 copy) ----
        {
            const uint4* bp = (const uint4*)(Bt + (size_t)(bn + brow_n) * K + k0 + bhalf * 32);
#pragma unroll
            for (int i = 0; i < 4; i++)
                *(uint4*)&Bs[brow_n][bhalf * 32 + i * 8] = bp[i];
        }
        __syncthreads();

#pragma unroll
        for (int ks = 0; ks < TBK / 16; ks++) {
            int kb = ks * 16;
            unsigned a[4][4];
#pragma unroll
            for (int mt = 0; mt < 4; mt++)
                ldsm_x4(a[mt][0], a[mt][1], a[mt][2], a[mt][3],
                        &As[wm + mt * 16 + (lane & 15)][kb + (lane >> 4) * 8]);
            unsigned b[4][2];
#pragma unroll
            for (int j = 0; j < 2; j++) {
                unsigned r0, r1, r2, r3;
                ldsm_x4(r0, r1, r2, r3,
                        &Bs[wn + j * 16 + ((lane >> 4) << 3) + (lane & 7)]
                          [kb + ((lane >> 3) & 1) * 8]);
                b[2 * j][0] = r0; b[2 * j][1] = r1;
                b[2 * j + 1][0] = r2; b[2 * j + 1][1] = r3;
            }
#pragma unroll
            for (int mt = 0; mt < 4; mt++)
#pragma unroll
                for (int nt = 0; nt < 4; nt++) {
                    asm volatile(
                        "mma.sync.aligned.m16n8k16.row.col.f32.bf16.bf16.f32 "
                        "{%0,%1,%2,%3}, {%4,%5,%6,%7}, {%8,%9}, {%0,%1,%2,%3};\n"
                        : "+f"(acc[mt][nt][0]), "+f"(acc[mt][nt][1]),
                          "+f"(acc[mt][nt][2]), "+f"(acc[mt][nt][3])
                        : "r"(a[mt][0]), "r"(a[mt][1]), "r"(a[mt][2]), "r"(a[mt][3]),
                          "r"(b[nt][0]), "r"(b[nt][1]));
                }
        }
        __syncthreads();
    }

    bool bf_side = (bn < ncols_bf);   // whole 64-col tile is on one side
#pragma unroll
    for (int mt = 0; mt < 4; mt++) {
        int row0 = bm + wm + mt * 16 + tr;
#pragma unroll
        for (int nt = 0; nt < 4; nt++) {
            int col0 = bn + wn + nt * 8 + 2 * tc;
            if (bf_side) {
                if (row0 < M)
                    g_xlb[(size_t)row0 * (F1 / 2) + (col0 >> 1)] =
                        __floats2bfloat162_rn(acc[mt][nt][0], acc[mt][nt][1]);
                if (row0 + 8 < M)
                    g_xlb[(size_t)(row0 + 8) * (F1 / 2) + (col0 >> 1)] =
                        __floats2bfloat162_rn(acc[mt][nt][2], acc[mt][nt][3]);
            } else {
                int c = col0 - ncols_bf;
                if (row0 < M)
                    *(float2*)(Cf + (size_t)row0 * cf_stride + c) =
                        make_float2(acc[mt][nt][0], acc[mt][nt][1]);
                if (row0 + 8 < M)
                    *(float2*)(Cf + (size_t)(row0 + 8) * cf_stride + c) =
                        make_float2(acc[mt][nt][2], acc[mt][nt][3]);
            }
        }
    }
}

// ---------------- fused layer-1 attention (bf16 gather, online softmax) ----------------
__global__ void k_l1_fused(const float* __restrict__ att1, const float* __restrict__ b1) {
    int node = blockIdx.x;
    int c4 = threadIdx.x;                        // owns channels [4*c4, 4*c4+4)
    int beg = g_off[node], end = g_off[node + 1];

    float4 xr = *(const float4*)(g_xr + (size_t)node * F1 + c4 * 4);
    float4 aw = __ldg(&((const float4*)att1)[c4]);

    float m = -1e30f, den = 0.f;
    float4 acc = make_float4(0.f, 0.f, 0.f, 0.f);

    for (int p = beg; p < end; p++) {
        int src = g_csrc[p];                     // uniform per warp
        uint2 raw = *(const uint2*)(g_xlb + (size_t)src * (F1 / 2) + c4 * 2);
        float2 f0 = __bfloat1622float2(*(const __nv_bfloat162*)&raw.x);
        float2 f1 = __bfloat1622float2(*(const __nv_bfloat162*)&raw.y);
        float part = lrelu(f0.x + xr.x) * aw.x
                   + lrelu(f0.y + xr.y) * aw.y
                   + lrelu(f1.x + xr.z) * aw.z
                   + lrelu(f1.y + xr.w) * aw.w;
#pragma unroll
        for (int o = 8; o; o >>= 1)
            part += __shfl_xor_sync(0xffffffffu, part, o);
        if (part > m) {
            float sc = __expf(m - part);
            den *= sc;
            acc.x *= sc; acc.y *= sc; acc.z *= sc; acc.w *= sc;
            m = part;
        }
        float w = __expf(part - m);
        den += w;
        acc.x += w * f0.x; acc.y += w * f0.y; acc.z += w * f1.x; acc.w += w * f1.y;
    }
    float inv = 1.f / (den + 1e-16f);
    float4 bb = __ldg(&((const float4*)b1)[c4]);
    float r0 = acc.x * inv + bb.x;
    float r1 = acc.y * inv + bb.y;
    float r2 = acc.z * inv + bb.z;
    float r3 = acc.w * inv + bb.w;
    r0 = r0 > 0.f ? r0 : expm1f(r0);
    r1 = r1 > 0.f ? r1 : expm1f(r1);
    r2 = r2 > 0.f ? r2 : expm1f(r2);
    r3 = r3 > 0.f ? r3 : expm1f(r3);
    // store h1 as bf16 (GEMM2 A operand) — same rounding GEMM2 would apply anyway
    __nv_bfloat162 o0 = __floats2bfloat162_rn(r0, r1);
    __nv_bfloat162 o1 = __floats2bfloat162_rn(r2, r3);
    uint2 pk;
    pk.x = *(unsigned*)&o0;
    pk.y = *(unsigned*)&o1;
    *(uint2*)(g_h1b + (size_t)node * F1 + c4 * 4) = pk;
}

// ---------------- fused layer-2 attention + bias + log_softmax ----------------
__global__ void k_l2_fused(float* __restrict__ out, const float* __restrict__ att2,
                           const float* __restrict__ b2) {
    int node = (blockIdx.x * blockDim.x + threadIdx.x) >> 5;
    int lane = threadIdx.x & 31;
    if (node >= NN) return;
    int beg = g_off[node], end = g_off[node + 1];

    float xr = g_h2[(size_t)node * D2P + DOUT + lane];
    float aw = __ldg(att2 + lane);

    float m = -1e30f, den = 0.f, acc = 0.f;
    for (int p = beg; p < end; p++) {
        int src = g_csrc[p];
        float v = g_h2[(size_t)src * D2P + lane];
        float part = lrelu(v + xr) * aw;
#pragma unroll
        for (int o = 16; o; o >>= 1)
            part += __shfl_xor_sync(0xffffffffu, part, o);
        if (part > m) {
            float sc = __expf(m - part);
            den *= sc; acc *= sc; m = part;
        }
        float w = __expf(part - m);
        den += w;
        acc += w * v;
    }
    float v = acc / (den + 1e-16f) + __ldg(b2 + lane);
    float mx = v;
#pragma unroll
    for (int o = 16; o; o >>= 1) mx = fmaxf(mx, __shfl_xor_sync(0xffffffffu, mx, o));
    float s = __expf(v - mx);
#pragma unroll
    for (int o = 16; o; o >>= 1) s += __shfl_xor_sync(0xffffffffu, s, o);
    out[node * DOUT + lane] = v - mx - __logf(s);
}

// ---------------- launch ----------------
extern "C" void kernel_launch(void* const* d_in, const int* in_sizes, int n_in,
                              void* d_out, int out_size) {
    const float* x    = (const float*)d_in[0];
    const void*  ei   = d_in[1];
    const float* W1l  = (const float*)d_in[2];
    const float* W1r  = (const float*)d_in[3];
    const float* att1 = (const float*)d_in[4];
    const float* b1   = (const float*)d_in[5];
    const float* W2l  = (const float*)d_in[6];
    const float* W2r  = (const float*)d_in[7];
    const float* att2 = (const float*)d_in[8];
    const float* b2   = (const float*)d_in[9];
    float*       out  = (float*)d_out;

    const int TPB = 256;

    float *xr, *h2;
    __nv_bfloat16 *w1t, *w2t, *h1b;
    cudaGetSymbolAddress((void**)&xr,  g_xr);
    cudaGetSymbolAddress((void**)&h2,  g_h2);
    cudaGetSymbolAddress((void**)&w1t, g_W1Tb);
    cudaGetSymbolAddress((void**)&w2t, g_W2Tb);
    cudaGetSymbolAddress((void**)&h1b, g_h1b);

    k_prep<<<(NN + TPB - 1) / TPB, TPB>>>(ei);                          // 1
    k_decode_count<<<(ETOT + TPB - 1) / TPB, TPB>>>(ei);                // 2
    k_packT1<<<dim3(F1P / 32, DIN / 32), dim3(32, 8)>>>(W1l, W1r);      // 3
    k_packT2<<<dim3(D2P / 32, F1 / 32), dim3(32, 8)>>>(W2l, W2r);       // 4
    {
        dim3 grid(F1P / TBN, (NN + TBM - 1) / TBM);
        k_gemm_bf16<<<grid, 128>>>(x, nullptr, w1t, xr, NN, DIN, 0, F1, F1); // 5
    }
    k_scan<<<1, SCAN_T>>>();                                            // 6
    k_fill<<<(ETOT + TPB - 1) / TPB, TPB>>>();                          // 7
    k_l1_fused<<<NN, 128>>>(att1, b1);                                  // 8
    {
        dim3 grid(D2P / TBN, (NN + TBM - 1) / TBM);
        k_gemm_bf16<<<grid, 128>>>(nullptr, h1b, w2t, h2, NN, F1, 1, 0, D2P); // 9
    }
    k_l2_fused<<<(NN * 32 + TPB - 1) / TPB, TPB>>>(out, att2, b2);      // 10
}

// round 13
// speedup vs baseline: 1.3939x; 1.1685x over previous
#include <cuda_runtime.h>
#include <cuda_bf16.h>
#include <math.h>

#define NN    10000
#define EE    320000
#define ETOT  330000
#define DIN   256
#define HEADS 8
#define C1    64
#define F1    512
#define F1P   1024            // packed xl|xr GEMM width
#define DOUT  32
#define D2P   64              // packed h2l|h2r row
#define NEG   0.2f

// ---------------- scratch ----------------
__device__ int             g_src[ETOT];
__device__ int             g_dst[ETOT];
__device__ int             g_mode64;
__device__ int             g_deg[NN];
__device__ int             g_off[NN + 1];
__device__ int             g_cur[NN];
__device__ int             g_csrc[ETOT];          // src id sorted by dst
__device__ __nv_bfloat16   g_W1Tb[F1P * DIN];     // [n][k] transposed bf16 [1024][256]
__device__ __nv_bfloat16   g_W2Tb[D2P * F1];      // [n][k] transposed bf16 [64][512]
__device__ __nv_bfloat16   g_xb[NN * DIN];        // x converted to bf16
__device__ __nv_bfloat162  g_xlb[NN * (F1 / 2)];  // xl half, bf16x2 (gather operand)
__device__ float           g_xr[NN * F1];         // xr half, fp32
__device__ __nv_bfloat16   g_h1b[NN * F1];        // elu'd h1, bf16 (GEMM2 A operand)
__device__ float           g_h2[NN * D2P];        // per node: [h2l(32) | h2r(32)]

__device__ __forceinline__ float lrelu(float v) { return v > 0.f ? v : NEG * v; }

// ---------------- setup: zero deg + dtype probe ----------------
__global__ void k_prep(const void* __restrict__ ei) {
    int i = blockIdx.x * blockDim.x + threadIdx.x;
    if (i < NN) g_deg[i] = 0;
    if (blockIdx.x == 0 && threadIdx.x == 0) {
        const long long* p64 = (const long long*)ei;
        int ok = 1;
        for (int j = 0; j < 64; j++) {
            long long v = p64[j];
            if (v < 0 || v >= NN) { ok = 0; break; }
        }
        g_mode64 = ok;
    }
}

// ---------------- decode + degree count ----------------
__global__ void k_decode_count(const void* __restrict__ ei) {
    int e = blockIdx.x * blockDim.x + threadIdx.x;
    if (e >= ETOT) return;
    int s, d;
    if (e >= EE) { s = d = e - EE; }
    else if (g_mode64) {
        s = (int)((const long long*)ei)[e];
        d = (int)((const long long*)ei)[EE + e];
    } else {
        s = ((const int*)ei)[e];
        d = ((const int*)ei)[EE + e];
    }
    g_src[e] = s;
    g_dst[e] = d;
    atomicAdd(&g_deg[d], 1);
}

// ---------------- scan ----------------
#define SCAN_T 1024
#define SCAN_PER ((NN + SCAN_T - 1) / SCAN_T)
__global__ void k_scan() {
    __shared__ int s[SCAN_T];
    int t = threadIdx.x;
    int base = t * SCAN_PER;
    int sum = 0;
#pragma unroll
    for (int i = 0; i < SCAN_PER; i++) {
        int idx = base + i;
        if (idx < NN) sum += g_deg[idx];
    }
    s[t] = sum;
    __syncthreads();
    for (int o = 1; o < SCAN_T; o <<= 1) {
        int v = (t >= o) ? s[t - o] : 0;
        __syncthreads();
        s[t] += v;
        __syncthreads();
    }
    int run = s[t] - sum;
#pragma unroll
    for (int i = 0; i < SCAN_PER; i++) {
        int idx = base + i;
        if (idx < NN) {
            g_off[idx] = run;
            g_cur[idx] = run;
            run += g_deg[idx];
        }
    }
    if (t == SCAN_T - 1) g_off[NN] = ETOT;
}

__global__ void k_fill() {
    int e = blockIdx.x * blockDim.x + threadIdx.x;
    if (e >= ETOT) return;
    int pos = atomicAdd(&g_cur[g_dst[e]], 1);
    g_csrc[pos] = g_src[e];
}

// ---------------- merged: transpose-pack W1,W2 (bf16 [n][k]) + convert x->bf16 ----------------
// blocks [0,256): W1 tiles; [256,288): W2 tiles; [288,2788): x conversion
#define PACKB_W1 256
#define PACKB_W2 32
#define PACKB_X  2500
__global__ void k_pack_all(const float* __restrict__ W1l, const float* __restrict__ W1r,
                           const float* __restrict__ W2l, const float* __restrict__ W2r,
                           const float* __restrict__ x) {
    __shared__ float tile[32][33];
    int b = blockIdx.x;
    int tid = threadIdx.x;
    if (b < PACKB_W1) {
        int n0 = (b & 31) * 32, k0 = (b >> 5) * 32;
        int tx = tid & 31, ty = tid >> 5;   // ty 0..7
#pragma unroll
        for (int i = 0; i < 32; i += 8) {
            int k = k0 + ty + i, n = n0 + tx;
            float v = (n < F1) ? W1l[k * F1 + n] : W1r[k * F1 + (n - F1)];
            tile[ty + i][tx] = v;
        }
        __syncthreads();
#pragma unroll
        for (int i = 0; i < 32; i += 8) {
            int n = n0 + ty + i, k = k0 + tx;
            g_W1Tb[(size_t)n * DIN + k] = __float2bfloat16(tile[tx][ty + i]);
        }
    } else if (b < PACKB_W1 + PACKB_W2) {
        int r = b - PACKB_W1;
        int n0 = (r & 1) * 32, k0 = (r >> 1) * 32;
        int tx = tid & 31, ty = tid >> 5;
#pragma unroll
        for (int i = 0; i < 32; i += 8) {
            int k = k0 + ty + i, n = n0 + tx;
            float v = (n < DOUT) ? W2l[k * DOUT + n] : W2r[k * DOUT + (n - DOUT)];
            tile[ty + i][tx] = v;
        }
        __syncthreads();
#pragma unroll
        for (int i = 0; i < 32; i += 8) {
            int n = n0 + ty + i, k = k0 + tx;
            g_W2Tb[(size_t)n * F1 + k] = __float2bfloat16(tile[tx][ty + i]);
        }
    } else {
        int idx = (b - PACKB_W1 - PACKB_W2) * 1024 + tid * 4;  // 4 floats per thread
        float4 v = *(const float4*)(x + idx);
        __nv_bfloat162 p0 = __floats2bfloat162_rn(v.x, v.y);
        __nv_bfloat162 p1 = __floats2bfloat162_rn(v.z, v.w);
        uint2 pk;
        pk.x = *(unsigned*)&p0;
        pk.y = *(unsigned*)&p1;
        *(uint2*)(g_xb + idx) = pk;
    }
}

// ---------------- bf16 tensor-core GEMM: cp.async double-buffer + swizzle ----------------
// C = A[M,K] @ Bt^T, A bf16 row-major, Bt [Nc][K] bf16 n-major.
// Epilogue: cols < ncols_bf -> bf16x2 to g_xlb; rest -> fp32 Cf (stride cf_stride).
#define TBM 128
#define TBN 64
#define TBK 64
#define STAGE_BYTES 24576           // A: 128*128, B: 64*128
__device__ __forceinline__ void cp16(unsigned dst, const void* src, unsigned sz) {
    asm volatile("cp.async.cg.shared.global [%0], [%1], 16, %2;\n"
                 :: "r"(dst), "l"(src), "r"(sz));
}
__device__ __forceinline__ void ldsm_x4(unsigned& r0, unsigned& r1, unsigned& r2, unsigned& r3,
                                        const void* p) {
    unsigned addr = (unsigned)__cvta_generic_to_shared(p);
    asm volatile("ldmatrix.sync.aligned.m8n8.x4.shared.b16 {%0,%1,%2,%3}, [%4];"
                 : "=r"(r0), "=r"(r1), "=r"(r2), "=r"(r3) : "r"(addr));
}

__global__ void __launch_bounds__(128) k_gemm_bf16(
    const __nv_bfloat16* __restrict__ A,
    const __nv_bfloat16* __restrict__ Bt, float* __restrict__ Cf,
    int M, int K, int ncols_bf, int cf_stride) {
    __shared__ char smem[2 * STAGE_BYTES];

    int tid = threadIdx.x;
    int warp = tid >> 5, lane = tid & 31;
    int wm = (warp & 1) * 64;
    int wn = (warp >> 1) * 32;
    int bm = blockIdx.y * TBM, bn = blockIdx.x * TBN;
    int tr = lane >> 2, tc = lane & 3;

    float acc[4][4][4];
#pragma unroll
    for (int mt = 0; mt < 4; mt++)
#pragma unroll
        for (int nt = 0; nt < 4; nt++)
#pragma unroll
            for (int r = 0; r < 4; r++) acc[mt][nt][r] = 0.f;

    // fill helper: one stage of A (128 rows x 128B) + B (64 rows x 128B), swizzled
    auto fill = [&](int stage, int k0) {
        char* base = smem + stage * STAGE_BYTES;
        int row = tid;
        unsigned valid = (bm + row < M) ? 16u : 0u;
        const char* asrc = (const char*)(A + (size_t)(bm + row) * K + k0);
        unsigned adst = (unsigned)__cvta_generic_to_shared(base + row * 128);
#pragma unroll
        for (int c = 0; c < 8; c++)
            cp16(adst + (((c ^ (row & 7))) << 4), asrc + c * 16, valid);
        int nrow = tid & 63, half = tid >> 6;
        const char* bsrc = (const char*)(Bt + (size_t)(bn + nrow) * K + k0);
        unsigned bdst = (unsigned)__cvta_generic_to_shared(base + 16384 + nrow * 128);
#pragma unroll
        for (int i = 0; i < 4; i++) {
            int c = half * 4 + i;
            cp16(bdst + (((c ^ (nrow & 7))) << 4), bsrc + c * 16, 16u);
        }
        asm volatile("cp.async.commit_group;\n");
    };

    int KT = K / TBK;
    fill(0, 0);
    for (int kt = 0; kt < KT; kt++) {
        if (kt + 1 < KT) {
            fill((kt + 1) & 1, (kt + 1) * TBK);
            asm volatile("cp.async.wait_group 1;\n");
        } else {
            asm volatile("cp.async.wait_group 0;\n");
        }
        __syncthreads();

        char* Ab_s = smem + (kt & 1) * STAGE_BYTES;
        char* Bb_s = Ab_s + 16384;
#pragma unroll
        for (int ks = 0; ks < TBK / 16; ks++) {
            unsigned a[4][4];
#pragma unroll
            for (int mt = 0; mt < 4; mt++) {
                int row = wm + mt * 16 + (lane & 15);
                int chunk = ks * 2 + (lane >> 4);
                ldsm_x4(a[mt][0], a[mt][1], a[mt][2], a[mt][3],
                        Ab_s + row * 128 + ((chunk ^ (row & 7)) << 4));
            }
            unsigned b[4][2];
#pragma unroll
            for (int j = 0; j < 2; j++) {
                int row = wn + j * 16 + ((lane >> 4) << 3) + (lane & 7);
                int chunk = ks * 2 + ((lane >> 3) & 1);
                unsigned r0, r1, r2, r3;
                ldsm_x4(r0, r1, r2, r3,
                        Bb_s + row * 128 + ((chunk ^ (row & 7)) << 4));
                b[2 * j][0] = r0; b[2 * j][1] = r1;
                b[2 * j + 1][0] = r2; b[2 * j + 1][1] = r3;
            }
#pragma unroll
            for (int mt = 0; mt < 4; mt++)
#pragma unroll
                for (int nt = 0; nt < 4; nt++) {
                    asm volatile(
                        "mma.sync.aligned.m16n8k16.row.col.f32.bf16.bf16.f32 "
                        "{%0,%1,%2,%3}, {%4,%5,%6,%7}, {%8,%9}, {%0,%1,%2,%3};\n"
                        : "+f"(acc[mt][nt][0]), "+f"(acc[mt][nt][1]),
                          "+f"(acc[mt][nt][2]), "+f"(acc[mt][nt][3])
                        : "r"(a[mt][0]), "r"(a[mt][1]), "r"(a[mt][2]), "r"(a[mt][3]),
                          "r"(b[nt][0]), "r"(b[nt][1]));
                }
        }
        __syncthreads();
    }

    bool bf_side = (bn < ncols_bf);
#pragma unroll
    for (int mt = 0; mt < 4; mt++) {
        int row0 = bm + wm + mt * 16 + tr;
#pragma unroll
        for (int nt = 0; nt < 4; nt++) {
            int col0 = bn + wn + nt * 8 + 2 * tc;
            if (bf_side) {
                if (row0 < M)
                    g_xlb[(size_t)row0 * (F1 / 2) + (col0 >> 1)] =
                        __floats2bfloat162_rn(acc[mt][nt][0], acc[mt][nt][1]);
                if (row0 + 8 < M)
                    g_xlb[(size_t)(row0 + 8) * (F1 / 2) + (col0 >> 1)] =
                        __floats2bfloat162_rn(acc[mt][nt][2], acc[mt][nt][3]);
            } else {
                int c = col0 - ncols_bf;
                if (row0 < M)
                    *(float2*)(Cf + (size_t)row0 * cf_stride + c) =
                        make_float2(acc[mt][nt][0], acc[mt][nt][1]);
                if (row0 + 8 < M)
                    *(float2*)(Cf + (size_t)(row0 + 8) * cf_stride + c) =
                        make_float2(acc[mt][nt][2], acc[mt][nt][3]);
            }
        }
    }
}

// ---------------- fused layer-1 attention (bf16 gather, online softmax) ----------------
__global__ void k_l1_fused(const float* __restrict__ att1, const float* __restrict__ b1) {
    int node = blockIdx.x;
    int c4 = threadIdx.x;                        // owns channels [4*c4, 4*c4+4)
    int beg = g_off[node], end = g_off[node + 1];

    float4 xr = *(const float4*)(g_xr + (size_t)node * F1 + c4 * 4);
    float4 aw = __ldg(&((const float4*)att1)[c4]);

    float m = -1e30f, den = 0.f;
    float4 acc = make_float4(0.f, 0.f, 0.f, 0.f);

    for (int p = beg; p < end; p++) {
        int src = g_csrc[p];                     // uniform per warp
        uint2 raw = *(const uint2*)(g_xlb + (size_t)src * (F1 / 2) + c4 * 2);
        float2 f0 = __bfloat1622float2(*(const __nv_bfloat162*)&raw.x);
        float2 f1 = __bfloat1622float2(*(const __nv_bfloat162*)&raw.y);
        float part = lrelu(f0.x + xr.x) * aw.x
                   + lrelu(f0.y + xr.y) * aw.y
                   + lrelu(f1.x + xr.z) * aw.z
                   + lrelu(f1.y + xr.w) * aw.w;
#pragma unroll
        for (int o = 8; o; o >>= 1)
            part += __shfl_xor_sync(0xffffffffu, part, o);
        if (part > m) {
            float sc = __expf(m - part);
            den *= sc;
            acc.x *= sc; acc.y *= sc; acc.z *= sc; acc.w *= sc;
            m = part;
        }
        float w = __expf(part - m);
        den += w;
        acc.x += w * f0.x; acc.y += w * f0.y; acc.z += w * f1.x; acc.w += w * f1.y;
    }
    float inv = 1.f / (den + 1e-16f);
    float4 bb = __ldg(&((const float4*)b1)[c4]);
    float r0 = acc.x * inv + bb.x;
    float r1 = acc.y * inv + bb.y;
    float r2 = acc.z * inv + bb.z;
    float r3 = acc.w * inv + bb.w;
    r0 = r0 > 0.f ? r0 : expm1f(r0);
    r1 = r1 > 0.f ? r1 : expm1f(r1);
    r2 = r2 > 0.f ? r2 : expm1f(r2);
    r3 = r3 > 0.f ? r3 : expm1f(r3);
    __nv_bfloat162 o0 = __floats2bfloat162_rn(r0, r1);
    __nv_bfloat162 o1 = __floats2bfloat162_rn(r2, r3);
    uint2 pk;
    pk.x = *(unsigned*)&o0;
    pk.y = *(unsigned*)&o1;
    *(uint2*)(g_h1b + (size_t)node * F1 + c4 * 4) = pk;
}

// ---------------- fused layer-2 attention + bias + log_softmax ----------------
__global__ void k_l2_fused(float* __restrict__ out, const float* __restrict__ att2,
                           const float* __restrict__ b2) {
    int node = (blockIdx.x * blockDim.x + threadIdx.x) >> 5;
    int lane = threadIdx.x & 31;
    if (node >= NN) return;
    int beg = g_off[node], end = g_off[node + 1];

    float xr = g_h2[(size_t)node * D2P + DOUT + lane];
    float aw = __ldg(att2 + lane);

    float m = -1e30f, den = 0.f, acc = 0.f;
    for (int p = beg; p < end; p++) {
        int src = g_csrc[p];
        float v = g_h2[(size_t)src * D2P + lane];
        float part = lrelu(v + xr) * aw;
#pragma unroll
        for (int o = 16; o; o >>= 1)
            part += __shfl_xor_sync(0xffffffffu, part, o);
        if (part > m) {
            float sc = __expf(m - part);
            den *= sc; acc *= sc; m = part;
        }
        float w = __expf(part - m);
        den += w;
        acc += w * v;
    }
    float v = acc / (den + 1e-16f) + __ldg(b2 + lane);
    float mx = v;
#pragma unroll
    for (int o = 16; o; o >>= 1) mx = fmaxf(mx, __shfl_xor_sync(0xffffffffu, mx, o));
    float s = __expf(v - mx);
#pragma unroll
    for (int o = 16; o; o >>= 1) s += __shfl_xor_sync(0xffffffffu, s, o);
    out[node * DOUT + lane] = v - mx - __logf(s);
}

// ---------------- launch ----------------
extern "C" void kernel_launch(void* const* d_in, const int* in_sizes, int n_in,
                              void* d_out, int out_size) {
    const float* x    = (const float*)d_in[0];
    const void*  ei   = d_in[1];
    const float* W1l  = (const float*)d_in[2];
    const float* W1r  = (const float*)d_in[3];
    const float* att1 = (const float*)d_in[4];
    const float* b1   = (const float*)d_in[5];
    const float* W2l  = (const float*)d_in[6];
    const float* W2r  = (const float*)d_in[7];
    const float* att2 = (const float*)d_in[8];
    const float* b2   = (const float*)d_in[9];
    float*       out  = (float*)d_out;

    const int TPB = 256;

    float *xr, *h2;
    __nv_bfloat16 *w1t, *w2t, *h1b, *xb;
    cudaGetSymbolAddress((void**)&xr,  g_xr);
    cudaGetSymbolAddress((void**)&h2,  g_h2);
    cudaGetSymbolAddress((void**)&w1t, g_W1Tb);
    cudaGetSymbolAddress((void**)&w2t, g_W2Tb);
    cudaGetSymbolAddress((void**)&h1b, g_h1b);
    cudaGetSymbolAddress((void**)&xb,  g_xb);

    k_prep<<<(NN + TPB - 1) / TPB, TPB>>>(ei);                          // 1
    k_decode_count<<<(ETOT + TPB - 1) / TPB, TPB>>>(ei);                // 2
    k_pack_all<<<PACKB_W1 + PACKB_W2 + PACKB_X, TPB>>>(W1l, W1r, W2l, W2r, x); // 3
    {
        dim3 grid(F1P / TBN, (NN + TBM - 1) / TBM);
        k_gemm_bf16<<<grid, 128>>>(xb, w1t, xr, NN, DIN, F1, F1);       // 4
    }
    k_scan<<<1, SCAN_T>>>();                                            // 5
    k_fill<<<(ETOT + TPB - 1) / TPB, TPB>>>();                          // 6
    k_l1_fused<<<NN, 128>>>(att1, b1);                                  // 7
    {
        dim3 grid(1, (NN + TBM - 1) / TBM);
        k_gemm_bf16<<<grid, 128>>>(h1b, w2t, h2, NN, F1, 0, D2P);       // 8
    }
    k_l2_fused<<<(NN * 32 + TPB - 1) / TPB, TPB>>>(out, att2, b2);      // 9
}

// round 14
// speedup vs baseline: 1.5890x; 1.1400x over previous
#include <cuda_runtime.h>
#include <cuda_bf16.h>
#include <math.h>

#define NN    10000
#define EE    320000
#define ETOT  330000
#define DIN   256
#define HEADS 8
#define C1    64
#define F1    512
#define F1P   1024            // packed xl|xr GEMM width
#define DOUT  32
#define D2P   64              // packed h2l|h2r row
#define NEG   0.2f

// ---------------- scratch ----------------
__device__ int             g_src[ETOT];
__device__ int             g_dst[ETOT];
__device__ int             g_mode64;
__device__ int             g_deg[NN];
__device__ int             g_off[NN + 1];
__device__ int             g_cur[NN];
__device__ int             g_csrc[ETOT];          // src id sorted by dst
__device__ __nv_bfloat16   g_W1Tb[F1P * DIN];     // [n][k] transposed bf16 [1024][256]
__device__ __nv_bfloat16   g_W2Tb[D2P * F1];      // [n][k] transposed bf16 [64][512]
__device__ __nv_bfloat16   g_xb[NN * DIN];        // x converted to bf16
__device__ __nv_bfloat162  g_xlb[NN * (F1 / 2)];  // xl half, bf16x2 (gather operand)
__device__ float           g_xr[NN * F1];         // xr half, fp32
__device__ __nv_bfloat16   g_h1b[NN * F1];        // elu'd h1, bf16 (GEMM2 A operand)
__device__ float           g_h2[NN * D2P];        // per node: [h2l(32) | h2r(32)]

__device__ __forceinline__ float lrelu(float v) { return v > 0.f ? v : NEG * v; }

// ---------------- probe edge dtype (1 warp) ----------------
__global__ void k_prep(const void* __restrict__ ei) {
    if (threadIdx.x == 0) {
        const long long* p64 = (const long long*)ei;
        int ok = 1;
        for (int j = 0; j < 64; j++) {
            long long v = p64[j];
            if (v < 0 || v >= NN) { ok = 0; break; }
        }
        g_mode64 = ok;
    }
}

// ---------------- decode + degree count ----------------
__global__ void k_decode_count(const void* __restrict__ ei) {
    int e = blockIdx.x * blockDim.x + threadIdx.x;
    if (e >= ETOT) return;
    int s, d;
    if (e >= EE) { s = d = e - EE; }
    else if (g_mode64) {
        s = (int)((const long long*)ei)[e];
        d = (int)((const long long*)ei)[EE + e];
    } else {
        s = ((const int*)ei)[e];
        d = ((const int*)ei)[EE + e];
    }
    g_src[e] = s;
    g_dst[e] = d;
    atomicAdd(&g_deg[d], 1);
}

// ---------------- scan (also re-zeroes g_deg for the next graph replay) ----------------
#define SCAN_T 1024
#define SCAN_PER ((NN + SCAN_T - 1) / SCAN_T)
__global__ void k_scan() {
    __shared__ int s[SCAN_T];
    int t = threadIdx.x;
    int base = t * SCAN_PER;
    int deg[SCAN_PER];
    int sum = 0;
#pragma unroll
    for (int i = 0; i < SCAN_PER; i++) {
        int idx = base + i;
        deg[i] = (idx < NN) ? g_deg[idx] : 0;
        sum += deg[i];
        if (idx < NN) g_deg[idx] = 0;        // ready for next replay
    }
    s[t] = sum;
    __syncthreads();
    for (int o = 1; o < SCAN_T; o <<= 1) {
        int v = (t >= o) ? s[t - o] : 0;
        __syncthreads();
        s[t] += v;
        __syncthreads();
    }
    int run = s[t] - sum;
#pragma unroll
    for (int i = 0; i < SCAN_PER; i++) {
        int idx = base + i;
        if (idx < NN) {
            g_off[idx] = run;
            g_cur[idx] = run;
            run += deg[i];
        }
    }
    if (t == SCAN_T - 1) g_off[NN] = ETOT;
}

__global__ void k_fill() {
    int e = blockIdx.x * blockDim.x + threadIdx.x;
    if (e >= ETOT) return;
    int pos = atomicAdd(&g_cur[g_dst[e]], 1);
    g_csrc[pos] = g_src[e];
}

// ---------------- merged: transpose-pack W1,W2 (bf16 [n][k]) + convert x->bf16 ----------------
#define PACKB_W1 256
#define PACKB_W2 32
#define PACKB_X  2500
__global__ void k_pack_all(const float* __restrict__ W1l, const float* __restrict__ W1r,
                           const float* __restrict__ W2l, const float* __restrict__ W2r,
                           const float* __restrict__ x) {
    __shared__ float tile[32][33];
    int b = blockIdx.x;
    int tid = threadIdx.x;
    if (b < PACKB_W1) {
        int n0 = (b & 31) * 32, k0 = (b >> 5) * 32;
        int tx = tid & 31, ty = tid >> 5;
#pragma unroll
        for (int i = 0; i < 32; i += 8) {
            int k = k0 + ty + i, n = n0 + tx;
            float v = (n < F1) ? W1l[k * F1 + n] : W1r[k * F1 + (n - F1)];
            tile[ty + i][tx] = v;
        }
        __syncthreads();
#pragma unroll
        for (int i = 0; i < 32; i += 8) {
            int n = n0 + ty + i, k = k0 + tx;
            g_W1Tb[(size_t)n * DIN + k] = __float2bfloat16(tile[tx][ty + i]);
        }
    } else if (b < PACKB_W1 + PACKB_W2) {
        int r = b - PACKB_W1;
        int n0 = (r & 1) * 32, k0 = (r >> 1) * 32;
        int tx = tid & 31, ty = tid >> 5;
#pragma unroll
        for (int i = 0; i < 32; i += 8) {
            int k = k0 + ty + i, n = n0 + tx;
            float v = (n < DOUT) ? W2l[k * DOUT + n] : W2r[k * DOUT + (n - DOUT)];
            tile[ty + i][tx] = v;
        }
        __syncthreads();
#pragma unroll
        for (int i = 0; i < 32; i += 8) {
            int n = n0 + ty + i, k = k0 + tx;
            g_W2Tb[(size_t)n * F1 + k] = __float2bfloat16(tile[tx][ty + i]);
        }
    } else {
        int idx = (b - PACKB_W1 - PACKB_W2) * 1024 + tid * 4;
        float4 v = *(const float4*)(x + idx);
        __nv_bfloat162 p0 = __floats2bfloat162_rn(v.x, v.y);
        __nv_bfloat162 p1 = __floats2bfloat162_rn(v.z, v.w);
        uint2 pk;
        pk.x = *(unsigned*)&p0;
        pk.y = *(unsigned*)&p1;
        *(uint2*)(g_xb + idx) = pk;
    }
}

// ---------------- bf16 tensor-core GEMM (templated N-tile, cp.async 2-stage) ----------------
// C = A[M,K] @ Bt^T, A bf16 row-major, Bt [Nc][K] bf16 n-major. TBM=128, TBK=64.
#define TBM 128
#define TBK 64
__device__ __forceinline__ void cp16(unsigned dst, const void* src, unsigned sz) {
    asm volatile("cp.async.cg.shared.global [%0], [%1], 16, %2;\n"
                 :: "r"(dst), "l"(src), "r"(sz));
}
__device__ __forceinline__ void ldsm_x4(unsigned& r0, unsigned& r1, unsigned& r2, unsigned& r3,
                                        const void* p) {
    unsigned addr = (unsigned)__cvta_generic_to_shared(p);
    asm volatile("ldmatrix.sync.aligned.m8n8.x4.shared.b16 {%0,%1,%2,%3}, [%4];"
                 : "=r"(r0), "=r"(r1), "=r"(r2), "=r"(r3) : "r"(addr));
}

template <int BN>
__global__ void __launch_bounds__(BN * 2) k_gemm_bf16(
    const __nv_bfloat16* __restrict__ A,
    const __nv_bfloat16* __restrict__ Bt, float* __restrict__ Cf,
    int M, int K, int ncols_bf, int cf_stride) {
    constexpr int T = BN * 2;                 // threads
    constexpr int STAGE = 16384 + BN * 128;   // A tile + B tile bytes
    extern __shared__ char smem[];

    int tid = threadIdx.x;
    int warp = tid >> 5, lane = tid & 31;
    int wm = (warp & 1) * 64;
    int wn = (warp >> 1) * 32;
    int bm = blockIdx.y * TBM, bn = blockIdx.x * BN;
    int tr = lane >> 2, tc = lane & 3;

    float acc[4][4][4];
#pragma unroll
    for (int mt = 0; mt < 4; mt++)
#pragma unroll
        for (int nt = 0; nt < 4; nt++)
#pragma unroll
            for (int r = 0; r < 4; r++) acc[mt][nt][r] = 0.f;

    auto fill = [&](int stage, int k0) {
        char* base = smem + stage * STAGE;
#pragma unroll
        for (int c = tid; c < 1024; c += T) {      // A: 128 rows x 8 chunks
            int row = c >> 3, ch = c & 7;
            unsigned valid = (bm + row < M) ? 16u : 0u;
            cp16((unsigned)__cvta_generic_to_shared(base + row * 128 + (((ch ^ (row & 7))) << 4)),
                 A + (size_t)(bm + row) * K + k0 + ch * 8, valid);
        }
#pragma unroll
        for (int c = tid; c < BN * 8; c += T) {    // B: BN rows x 8 chunks
            int row = c >> 3, ch = c & 7;
            cp16((unsigned)__cvta_generic_to_shared(base + 16384 + row * 128 + (((ch ^ (row & 7))) << 4)),
                 Bt + (size_t)(bn + row) * K + k0 + ch * 8, 16u);
        }
        asm volatile("cp.async.commit_group;\n");
    };

    int KT = K / TBK;
    fill(0, 0);
    for (int kt = 0; kt < KT; kt++) {
        if (kt + 1 < KT) {
            fill((kt + 1) & 1, (kt + 1) * TBK);
            asm volatile("cp.async.wait_group 1;\n");
        } else {
            asm volatile("cp.async.wait_group 0;\n");
        }
        __syncthreads();

        char* Ab_s = smem + (kt & 1) * STAGE;
        char* Bb_s = Ab_s + 16384;
#pragma unroll
        for (int ks = 0; ks < TBK / 16; ks++) {
            unsigned a[4][4];
#pragma unroll
            for (int mt = 0; mt < 4; mt++) {
                int row = wm + mt * 16 + (lane & 15);
                int chunk = ks * 2 + (lane >> 4);
                ldsm_x4(a[mt][0], a[mt][1], a[mt][2], a[mt][3],
                        Ab_s + row * 128 + ((chunk ^ (row & 7)) << 4));
            }
            unsigned b[4][2];
#pragma unroll
            for (int j = 0; j < 2; j++) {
                int row = wn + j * 16 + ((lane >> 4) << 3) + (lane & 7);
                int chunk = ks * 2 + ((lane >> 3) & 1);
                unsigned r0, r1, r2, r3;
                ldsm_x4(r0, r1, r2, r3,
                        Bb_s + row * 128 + ((chunk ^ (row & 7)) << 4));
                b[2 * j][0] = r0; b[2 * j][1] = r1;
                b[2 * j + 1][0] = r2; b[2 * j + 1][1] = r3;
            }
#pragma unroll
            for (int mt = 0; mt < 4; mt++)
#pragma unroll
                for (int nt = 0; nt < 4; nt++) {
                    asm volatile(
                        "mma.sync.aligned.m16n8k16.row.col.f32.bf16.bf16.f32 "
                        "{%0,%1,%2,%3}, {%4,%5,%6,%7}, {%8,%9}, {%0,%1,%2,%3};\n"
                        : "+f"(acc[mt][nt][0]), "+f"(acc[mt][nt][1]),
                          "+f"(acc[mt][nt][2]), "+f"(acc[mt][nt][3])
                        : "r"(a[mt][0]), "r"(a[mt][1]), "r"(a[mt][2]), "r"(a[mt][3]),
                          "r"(b[nt][0]), "r"(b[nt][1]));
                }
        }
        __syncthreads();
    }

    bool bf_side = (bn < ncols_bf);
#pragma unroll
    for (int mt = 0; mt < 4; mt++) {
        int row0 = bm + wm + mt * 16 + tr;
#pragma unroll
        for (int nt = 0; nt < 4; nt++) {
            int col0 = bn + wn + nt * 8 + 2 * tc;
            if (bf_side) {
                if (row0 < M)
                    g_xlb[(size_t)row0 * (F1 / 2) + (col0 >> 1)] =
                        __floats2bfloat162_rn(acc[mt][nt][0], acc[mt][nt][1]);
                if (row0 + 8 < M)
                    g_xlb[(size_t)(row0 + 8) * (F1 / 2) + (col0 >> 1)] =
                        __floats2bfloat162_rn(acc[mt][nt][2], acc[mt][nt][3]);
            } else {
                int c = col0 - ncols_bf;
                if (row0 < M)
                    *(float2*)(Cf + (size_t)row0 * cf_stride + c) =
                        make_float2(acc[mt][nt][0], acc[mt][nt][1]);
                if (row0 + 8 < M)
                    *(float2*)(Cf + (size_t)(row0 + 8) * cf_stride + c) =
                        make_float2(acc[mt][nt][2], acc[mt][nt][3]);
            }
        }
    }
}

// ---------------- fused layer-1 attention (bf16 gather, online softmax, 2x unroll) ----------------
__global__ void k_l1_fused(const float* __restrict__ att1, const float* __restrict__ b1) {
    int node = blockIdx.x;
    int c4 = threadIdx.x;                        // owns channels [4*c4, 4*c4+4)
    int beg = g_off[node], end = g_off[node + 1];

    float4 xr = *(const float4*)(g_xr + (size_t)node * F1 + c4 * 4);
    float4 aw = __ldg(&((const float4*)att1)[c4]);

    float m = -1e30f, den = 0.f;
    float4 acc = make_float4(0.f, 0.f, 0.f, 0.f);

    int p = beg;
    for (; p + 2 <= end; p += 2) {
        int src0 = g_csrc[p], src1 = g_csrc[p + 1];
        uint2 raw0 = *(const uint2*)(g_xlb + (size_t)src0 * (F1 / 2) + c4 * 2);
        uint2 raw1 = *(const uint2*)(g_xlb + (size_t)src1 * (F1 / 2) + c4 * 2);
        float2 a0 = __bfloat1622float2(*(const __nv_bfloat162*)&raw0.x);
        float2 a1 = __bfloat1622float2(*(const __nv_bfloat162*)&raw0.y);
        float2 b0 = __bfloat1622float2(*(const __nv_bfloat162*)&raw1.x);
        float2 b1v = __bfloat1622float2(*(const __nv_bfloat162*)&raw1.y);
        float p0 = lrelu(a0.x + xr.x) * aw.x + lrelu(a0.y + xr.y) * aw.y
                 + lrelu(a1.x + xr.z) * aw.z + lrelu(a1.y + xr.w) * aw.w;
        float p1 = lrelu(b0.x + xr.x) * aw.x + lrelu(b0.y + xr.y) * aw.y
                 + lrelu(b1v.x + xr.z) * aw.z + lrelu(b1v.y + xr.w) * aw.w;
#pragma unroll
        for (int o = 8; o; o >>= 1) {
            p0 += __shfl_xor_sync(0xffffffffu, p0, o);
            p1 += __shfl_xor_sync(0xffffffffu, p1, o);
        }
        float mx = fmaxf(p0, p1);
        if (mx > m) {
            float sc = __expf(m - mx);
            den *= sc;
            acc.x *= sc; acc.y *= sc; acc.z *= sc; acc.w *= sc;
            m = mx;
        }
        float w0 = __expf(p0 - m), w1 = __expf(p1 - m);
        den += w0 + w1;
        acc.x += w0 * a0.x + w1 * b0.x;
        acc.y += w0 * a0.y + w1 * b0.y;
        acc.z += w0 * a1.x + w1 * b1v.x;
        acc.w += w0 * a1.y + w1 * b1v.y;
    }
    if (p < end) {
        int src = g_csrc[p];
        uint2 raw = *(const uint2*)(g_xlb + (size_t)src * (F1 / 2) + c4 * 2);
        float2 f0 = __bfloat1622float2(*(const __nv_bfloat162*)&raw.x);
        float2 f1 = __bfloat1622float2(*(const __nv_bfloat162*)&raw.y);
        float part = lrelu(f0.x + xr.x) * aw.x + lrelu(f0.y + xr.y) * aw.y
                   + lrelu(f1.x + xr.z) * aw.z + lrelu(f1.y + xr.w) * aw.w;
#pragma unroll
        for (int o = 8; o; o >>= 1)
            part += __shfl_xor_sync(0xffffffffu, part, o);
        if (part > m) {
            float sc = __expf(m - part);
            den *= sc;
            acc.x *= sc; acc.y *= sc; acc.z *= sc; acc.w *= sc;
            m = part;
        }
        float w = __expf(part - m);
        den += w;
        acc.x += w * f0.x; acc.y += w * f0.y; acc.z += w * f1.x; acc.w += w * f1.y;
    }
    float inv = 1.f / (den + 1e-16f);
    float4 bb = __ldg(&((const float4*)b1)[c4]);
    float r0 = acc.x * inv + bb.x;
    float r1 = acc.y * inv + bb.y;
    float r2 = acc.z * inv + bb.z;
    float r3 = acc.w * inv + bb.w;
    r0 = r0 > 0.f ? r0 : expm1f(r0);
    r1 = r1 > 0.f ? r1 : expm1f(r1);
    r2 = r2 > 0.f ? r2 : expm1f(r2);
    r3 = r3 > 0.f ? r3 : expm1f(r3);
    __nv_bfloat162 o0 = __floats2bfloat162_rn(r0, r1);
    __nv_bfloat162 o1 = __floats2bfloat162_rn(r2, r3);
    uint2 pk;
    pk.x = *(unsigned*)&o0;
    pk.y = *(unsigned*)&o1;
    *(uint2*)(g_h1b + (size_t)node * F1 + c4 * 4) = pk;
}

// ---------------- fused layer-2 attention + bias + log_softmax ----------------
__global__ void k_l2_fused(float* __restrict__ out, const float* __restrict__ att2,
                           const float* __restrict__ b2) {
    int node = (blockIdx.x * blockDim.x + threadIdx.x) >> 5;
    int lane = threadIdx.x & 31;
    if (node >= NN) return;
    int beg = g_off[node], end = g_off[node + 1];

    float xr = g_h2[(size_t)node * D2P + DOUT + lane];
    float aw = __ldg(att2 + lane);

    float m = -1e30f, den = 0.f, acc = 0.f;
    for (int p = beg; p < end; p++) {
        int src = g_csrc[p];
        float v = g_h2[(size_t)src * D2P + lane];
        float part = lrelu(v + xr) * aw;
#pragma unroll
        for (int o = 16; o; o >>= 1)
            part += __shfl_xor_sync(0xffffffffu, part, o);
        if (part > m) {
            float sc = __expf(m - part);
            den *= sc; acc *= sc; m = part;
        }
        float w = __expf(part - m);
        den += w;
        acc += w * v;
    }
    float v = acc / (den + 1e-16f) + __ldg(b2 + lane);
    float mx = v;
#pragma unroll
    for (int o = 16; o; o >>= 1) mx = fmaxf(mx, __shfl_xor_sync(0xffffffffu, mx, o));
    float s = __expf(v - mx);
#pragma unroll
    for (int o = 16; o; o >>= 1) s += __shfl_xor_sync(0xffffffffu, s, o);
    out[node * DOUT + lane] = v - mx - __logf(s);
}

// ---------------- launch ----------------
extern "C" void kernel_launch(void* const* d_in, const int* in_sizes, int n_in,
                              void* d_out, int out_size) {
    const float* x    = (const float*)d_in[0];
    const void*  ei   = d_in[1];
    const float* W1l  = (const float*)d_in[2];
    const float* W1r  = (const float*)d_in[3];
    const float* att1 = (const float*)d_in[4];
    const float* b1   = (const float*)d_in[5];
    const float* W2l  = (const float*)d_in[6];
    const float* W2r  = (const float*)d_in[7];
    const float* att2 = (const float*)d_in[8];
    const float* b2   = (const float*)d_in[9];
    float*       out  = (float*)d_out;

    const int TPB = 256;

    float *xr, *h2;
    __nv_bfloat16 *w1t, *w2t, *h1b, *xb;
    cudaGetSymbolAddress((void**)&xr,  g_xr);
    cudaGetSymbolAddress((void**)&h2,  g_h2);
    cudaGetSymbolAddress((void**)&w1t, g_W1Tb);
    cudaGetSymbolAddress((void**)&w2t, g_W2Tb);
    cudaGetSymbolAddress((void**)&h1b, g_h1b);
    cudaGetSymbolAddress((void**)&xb,  g_xb);

    const int SM1 = 2 * (16384 + 128 * 128);   // 65536
    const int SM2 = 2 * (16384 + 64 * 128);    // 49152
    cudaFuncSetAttribute(k_gemm_bf16<128>, cudaFuncAttributeMaxDynamicSharedMemorySize, SM1);
    cudaFuncSetAttribute(k_gemm_bf16<64>,  cudaFuncAttributeMaxDynamicSharedMemorySize, SM2);

    k_prep<<<1, 32>>>(ei);                                              // 1
    k_decode_count<<<(ETOT + TPB - 1) / TPB, TPB>>>(ei);                // 2
    k_pack_all<<<PACKB_W1 + PACKB_W2 + PACKB_X, TPB>>>(W1l, W1r, W2l, W2r, x); // 3
    {
        dim3 grid(F1P / 128, (NN + TBM - 1) / TBM);
        k_gemm_bf16<128><<<grid, 256, SM1>>>(xb, w1t, xr, NN, DIN, F1, F1); // 4
    }
    k_scan<<<1, SCAN_T>>>();                                            // 5
    k_fill<<<(ETOT + TPB - 1) / TPB, TPB>>>();                          // 6
    k_l1_fused<<<NN, 128>>>(att1, b1);                                  // 7
    {
        dim3 grid(1, (NN + TBM - 1) / TBM);
        k_gemm_bf16<64><<<grid, 128, SM2>>>(h1b, w2t, h2, NN, F1, 0, D2P); // 8
    }
    k_l2_fused<<<(NN * 32 + TPB - 1) / TPB, TPB>>>(out, att2, b2);      // 9
}